// round 16
// baseline (speedup 1.0000x reference)
#include <cuda_runtime.h>
#include <cuda_bf16.h>
#include <cstdint>

#define EPS   1.1920928955078125e-07f
#define SCALE 0.17677669529663687f   // 1/sqrt(32)

// ---------------------------------------------------------------------------
// scratch (static __device__ — no allocations allowed)
// ---------------------------------------------------------------------------
__device__ __align__(16) unsigned short g_cwp[36 * 9216];  // conv W bf16 [tap][ch][hi/lo] planes
__device__ __align__(16) unsigned short g_wqp[4 * 9216];   // qproj W bf16 planes
__device__ __align__(16) float g_wkt[128 * 128];           // kproj_w^T * normk_w
__device__ __align__(16) unsigned short g_qh[16384 * 128]; // q bf16 hi, [pixel][c], pre-scaled by SCALE
__device__ __align__(16) unsigned short g_ql[16384 * 128]; // q bf16 lo
__device__ __align__(16) unsigned short g_kh[1024 * 128];  // k bf16 hi, [pixel][c]
__device__ __align__(16) unsigned short g_kl[1024 * 128];
__device__ __align__(16) unsigned short g_vh[1024 * 128];  // v bf16 hi, [pixel][c]
__device__ __align__(16) unsigned short g_vl[1024 * 128];

// ---------------------------------------------------------------------------
// helpers
// ---------------------------------------------------------------------------
__device__ __forceinline__ uint32_t smem_u32(const void* p) {
    uint32_t a;
    asm("{ .reg .u64 t; cvta.to.shared.u64 t, %1; cvt.u32.u64 %0, t; }" : "=r"(a) : "l"(p));
    return a;
}
__device__ __forceinline__ void ldsm4(uint32_t& r0, uint32_t& r1, uint32_t& r2, uint32_t& r3,
                                      uint32_t addr) {
    asm volatile("ldmatrix.sync.aligned.m8n8.x4.shared.b16 {%0,%1,%2,%3}, [%4];"
                 : "=r"(r0), "=r"(r1), "=r"(r2), "=r"(r3) : "r"(addr));
}
__device__ __forceinline__ void ldsm4t(uint32_t& r0, uint32_t& r1, uint32_t& r2, uint32_t& r3,
                                       uint32_t addr) {
    asm volatile("ldmatrix.sync.aligned.m8n8.x4.trans.shared.b16 {%0,%1,%2,%3}, [%4];"
                 : "=r"(r0), "=r"(r1), "=r"(r2), "=r"(r3) : "r"(addr));
}
__device__ __forceinline__ void mma16816(float* c, const uint32_t* a, uint32_t b0, uint32_t b1) {
    asm volatile("mma.sync.aligned.m16n8k16.row.col.f32.bf16.bf16.f32 "
                 "{%0,%1,%2,%3}, {%4,%5,%6,%7}, {%8,%9}, {%0,%1,%2,%3};"
                 : "+f"(c[0]), "+f"(c[1]), "+f"(c[2]), "+f"(c[3])
                 : "r"(a[0]), "r"(a[1]), "r"(a[2]), "r"(a[3]), "r"(b0), "r"(b1));
}
__device__ __forceinline__ void cp16(uint32_t dst, const void* src) {
    asm volatile("cp.async.cg.shared.global [%0], [%1], 16;" :: "r"(dst), "l"(src));
}
#define CP_COMMIT() asm volatile("cp.async.commit_group;" ::: "memory")
#define CP_WAIT0()  asm volatile("cp.async.wait_group 0;" ::: "memory")

__device__ __forceinline__ void split2(float v0, float v1, uint32_t& hw, uint32_t& lw) {
    __nv_bfloat16 h0 = __float2bfloat16(v0), h1 = __float2bfloat16(v1);
    float r0 = v0 - __bfloat162float(h0), r1 = v1 - __bfloat162float(h1);
    __nv_bfloat16 l0 = __float2bfloat16(r0), l1 = __float2bfloat16(r1);
    hw = (uint32_t)__bfloat16_as_ushort(h0) | ((uint32_t)__bfloat16_as_ushort(h1) << 16);
    lw = (uint32_t)__bfloat16_as_ushort(l0) | ((uint32_t)__bfloat16_as_ushort(l1) << 16);
}
__device__ __forceinline__ void split1(float v, unsigned short& h, unsigned short& l) {
    __nv_bfloat16 hb = __float2bfloat16(v);
    __nv_bfloat16 lb = __float2bfloat16(v - __bfloat162float(hb));
    h = __bfloat16_as_ushort(hb);
    l = __bfloat16_as_ushort(lb);
}

// ---------------------------------------------------------------------------
// Kernel 0: weight prep (unchanged)
// ---------------------------------------------------------------------------
__global__ void prep_kernel(const float* __restrict__ conv_w,
                            const float* __restrict__ normq,
                            const float* __restrict__ normk,
                            const float* __restrict__ qw,
                            const float* __restrict__ kw) {
    int idx = blockIdx.x * 256 + threadIdx.x;
    if (idx < 147456) {
        int oc = idx & 127;
        int ci = (idx >> 7) & 127;
        int tap = idx >> 14;
        float w = conv_w[(oc * 128 + ci) * 9 + tap];
        __nv_bfloat16 h = __float2bfloat16(w);
        __nv_bfloat16 l = __float2bfloat16(w - __bfloat162float(h));
        int ch = ci >> 6, cl = ci & 63;
        size_t base = (size_t)((tap * 2 + ch) * 2) * 9216;
        g_cwp[base + oc * 72 + cl]        = __bfloat16_as_ushort(h);
        g_cwp[base + 9216 + oc * 72 + cl] = __bfloat16_as_ushort(l);
    }
    if (idx < 16384) {
        int o = idx & 127;
        int c = idx >> 7;
        g_wkt[idx] = kw[o * 128 + c] * normk[c];
        float v = qw[o * 128 + c] * normq[c];
        __nv_bfloat16 h = __float2bfloat16(v);
        __nv_bfloat16 l = __float2bfloat16(v - __bfloat162float(h));
        int ch = c >> 6, cl = c & 63;
        size_t base = (size_t)(ch * 2) * 9216;
        g_wqp[base + o * 72 + cl]        = __bfloat16_as_ushort(h);
        g_wqp[base + 9216 + o * 72 + cl] = __bfloat16_as_ushort(l);
    }
}

// ---------------------------------------------------------------------------
// Kernel 1: conv3x3 + RMSNorm + qproj via mma.sync. 512 threads (16 warps,
// 4M x 4N layout, warp tile 32x32) for 2x latency hiding on same smem.
// ---------------------------------------------------------------------------
__global__ __launch_bounds__(512, 1)
void convq_mma(const float* __restrict__ qin, const float* __restrict__ qb) {
    extern __shared__ char smc[];
    const int OF_PL = 48960;
    const int OF_B0 = 97920;
    const int OF_B1 = 134784;
    const int OF_SSQ  = 171648;   // 512 floats (2048 B)
    const int OF_RSTD = 173696;   // 128 floats
    const int OF_BIAS = 174208;   // 128 floats -> end 174720
    const int OF_CH = 0, OF_CL = 34816;

    const uint32_t sb = smem_u32(smc);
    const int tid = threadIdx.x;
    const int lane = tid & 31, wid = tid >> 5;
    const int warpM = wid & 3, warpN = wid >> 2;     // 4 x 4
    const int arow = lane & 15, khalf = lane >> 4;
    const int bn_off = (lane & 7) | ((lane >> 1) & 8);
    const int bk_half = (lane >> 3) & 1;

    float* sbias = (float*)(smc + OF_BIAS);
    if (tid < 128) sbias[tid] = qb[tid];

    {
        const char* src = (const char*)g_cwp;
        for (int j = tid; j < 2304; j += 512) cp16(sb + OF_B0 + j * 16, src + j * 16);
        CP_COMMIT();
    }

    {
        unsigned short* ph = (unsigned short*)smc;
        unsigned short* pl = (unsigned short*)(smc + OF_PL);
        const int gy0 = blockIdx.y * 8 - 1, gx0 = blockIdx.x * 16 - 1;
        for (int idx = tid; idx < 23040; idx += 512) {
            int ci = idx / 180, pix = idx - ci * 180;
            int py = pix / 18, px = pix - py * 18;
            int gy = gy0 + py, gx = gx0 + px;
            float x = 0.f;
            if ((unsigned)gy < 128u && (unsigned)gx < 128u) x = qin[ci * 16384 + gy * 128 + gx];
            unsigned short h, l;
            split1(x, h, l);
            ph[pix * 136 + ci] = h;
            pl[pix * 136 + ci] = l;
        }
    }

    int rowq[2], colq[2];
#pragma unroll
    for (int mf = 0; mf < 2; mf++) {
        int r = warpM * 32 + mf * 16 + arow;
        rowq[mf] = r >> 4;
        colq[mf] = r & 15;
    }

    float c[2][4][4];
#pragma unroll
    for (int mf = 0; mf < 2; mf++)
#pragma unroll
        for (int nf = 0; nf < 4; nf++)
#pragma unroll
            for (int j = 0; j < 4; j++) c[mf][nf][j] = 0.f;

    for (int i = 0; i < 18; i++) {
        CP_WAIT0();
        __syncthreads();
        if (i < 17) {
            const char* src = (const char*)g_cwp + (size_t)(i + 1) * 36864;
            const uint32_t dstb = sb + (((i + 1) & 1) ? OF_B1 : OF_B0);
            for (int j = tid; j < 2304; j += 512) cp16(dstb + j * 16, src + j * 16);
            CP_COMMIT();
        }
        const int tap = i >> 1, ch = i & 1;
        const int dy = tap / 3, dx = tap - dy * 3;
        const uint32_t Bh = sb + ((i & 1) ? OF_B1 : OF_B0);
        const uint32_t Bl = Bh + 18432;

        uint32_t apix[2];
#pragma unroll
        for (int mf = 0; mf < 2; mf++)
            apix[mf] = sb + ((rowq[mf] + dy) * 18 + colq[mf] + dx) * 272;

#pragma unroll
        for (int ks = 0; ks < 4; ks++) {
            const int acol2 = (ch * 64 + ks * 16 + khalf * 8) * 2;
            uint32_t ah[2][4], al[2][4];
            ldsm4(ah[0][0], ah[0][1], ah[0][2], ah[0][3], apix[0] + acol2);
            ldsm4(ah[1][0], ah[1][1], ah[1][2], ah[1][3], apix[1] + acol2);
            ldsm4(al[0][0], al[0][1], al[0][2], al[0][3], apix[0] + OF_PL + acol2);
            ldsm4(al[1][0], al[1][1], al[1][2], al[1][3], apix[1] + OF_PL + acol2);
            const int bofs = (warpN * 32 + bn_off) * 144 + (ks * 16 + bk_half * 8) * 2;
#pragma unroll
            for (int np = 0; np < 2; np++) {
                uint32_t bh0, bh1, bh2, bh3, bl0, bl1, bl2, bl3;
                ldsm4(bh0, bh1, bh2, bh3, Bh + bofs + np * 16 * 144);
                ldsm4(bl0, bl1, bl2, bl3, Bl + bofs + np * 16 * 144);
#pragma unroll
                for (int mf = 0; mf < 2; mf++) {
                    mma16816(c[mf][np * 2],     ah[mf], bh0, bh1);
                    mma16816(c[mf][np * 2 + 1], ah[mf], bh2, bh3);
                    mma16816(c[mf][np * 2],     ah[mf], bl0, bl1);
                    mma16816(c[mf][np * 2 + 1], ah[mf], bl2, bl3);
                    mma16816(c[mf][np * 2],     al[mf], bh0, bh1);
                    mma16816(c[mf][np * 2 + 1], al[mf], bh2, bh3);
                }
            }
        }
    }

    // ---- RMS reduction ----
    float s[2][2];
#pragma unroll
    for (int mf = 0; mf < 2; mf++) { s[mf][0] = 0.f; s[mf][1] = 0.f; }
#pragma unroll
    for (int mf = 0; mf < 2; mf++)
#pragma unroll
        for (int nf = 0; nf < 4; nf++) {
            s[mf][0] += c[mf][nf][0] * c[mf][nf][0] + c[mf][nf][1] * c[mf][nf][1];
            s[mf][1] += c[mf][nf][2] * c[mf][nf][2] + c[mf][nf][3] * c[mf][nf][3];
        }
#pragma unroll
    for (int off = 1; off <= 2; off <<= 1) {
#pragma unroll
        for (int mf = 0; mf < 2; mf++) {
            s[mf][0] += __shfl_xor_sync(0xffffffffu, s[mf][0], off);
            s[mf][1] += __shfl_xor_sync(0xffffffffu, s[mf][1], off);
        }
    }
    __syncthreads();   // all MMA reads of weight buffers done

    {
        const char* src = (const char*)g_wqp;
        for (int j = tid; j < 4608; j += 512) cp16(sb + OF_B0 + j * 16, src + j * 16);
        CP_COMMIT();
    }

    float* ssq2 = (float*)(smc + OF_SSQ);
    if ((lane & 3) == 0) {
#pragma unroll
        for (int mf = 0; mf < 2; mf++) {
            int r = warpM * 32 + mf * 16 + (lane >> 2);
            ssq2[warpN * 128 + r]     = s[mf][0];
            ssq2[warpN * 128 + r + 8] = s[mf][1];
        }
    }
    __syncthreads();
    float* rstd = (float*)(smc + OF_RSTD);
    if (tid < 128)
        rstd[tid] = rsqrtf((ssq2[tid] + ssq2[128 + tid] + ssq2[256 + tid] + ssq2[384 + tid])
                           * (1.0f / 128.0f) + EPS);
    __syncthreads();

    // ---- write normalized conv output planes (overlay patch) ----
#pragma unroll
    for (int mf = 0; mf < 2; mf++) {
        int r0 = warpM * 32 + mf * 16 + (lane >> 2);
        int r1 = r0 + 8;
        float s0 = rstd[r0], s1 = rstd[r1];
#pragma unroll
        for (int nf = 0; nf < 4; nf++) {
            int n = warpN * 32 + nf * 8 + 2 * (lane & 3);
            uint32_t hw, lw;
            split2(c[mf][nf][0] * s0, c[mf][nf][1] * s0, hw, lw);
            *(uint32_t*)(smc + OF_CH + r0 * 272 + n * 2) = hw;
            *(uint32_t*)(smc + OF_CL + r0 * 272 + n * 2) = lw;
            split2(c[mf][nf][2] * s1, c[mf][nf][3] * s1, hw, lw);
            *(uint32_t*)(smc + OF_CH + r1 * 272 + n * 2) = hw;
            *(uint32_t*)(smc + OF_CL + r1 * 272 + n * 2) = lw;
        }
    }
#pragma unroll
    for (int mf = 0; mf < 2; mf++)
#pragma unroll
        for (int nf = 0; nf < 4; nf++)
#pragma unroll
            for (int j = 0; j < 4; j++) c[mf][nf][j] = 0.f;
    CP_WAIT0();
    __syncthreads();

    // ---- qproj GEMM (K=128) ----
    {
        uint32_t arowaddr[2];
#pragma unroll
        for (int mf = 0; mf < 2; mf++)
            arowaddr[mf] = sb + (warpM * 32 + mf * 16 + arow) * 272;
#pragma unroll
        for (int ch = 0; ch < 2; ch++) {
            const uint32_t Bh = sb + OF_B0 + ch * 2 * 18432;
            const uint32_t Bl = Bh + 18432;
#pragma unroll
            for (int ks = 0; ks < 4; ks++) {
                const int acol2 = (ch * 64 + ks * 16 + khalf * 8) * 2;
                uint32_t ah[2][4], al[2][4];
                ldsm4(ah[0][0], ah[0][1], ah[0][2], ah[0][3], arowaddr[0] + OF_CH + acol2);
                ldsm4(ah[1][0], ah[1][1], ah[1][2], ah[1][3], arowaddr[1] + OF_CH + acol2);
                ldsm4(al[0][0], al[0][1], al[0][2], al[0][3], arowaddr[0] + OF_CL + acol2);
                ldsm4(al[1][0], al[1][1], al[1][2], al[1][3], arowaddr[1] + OF_CL + acol2);
                const int bofs = (warpN * 32 + bn_off) * 144 + (ks * 16 + bk_half * 8) * 2;
#pragma unroll
                for (int np = 0; np < 2; np++) {
                    uint32_t bh0, bh1, bh2, bh3, bl0, bl1, bl2, bl3;
                    ldsm4(bh0, bh1, bh2, bh3, Bh + bofs + np * 16 * 144);
                    ldsm4(bl0, bl1, bl2, bl3, Bl + bofs + np * 16 * 144);
#pragma unroll
                    for (int mf = 0; mf < 2; mf++) {
                        mma16816(c[mf][np * 2],     ah[mf], bh0, bh1);
                        mma16816(c[mf][np * 2 + 1], ah[mf], bh2, bh3);
                        mma16816(c[mf][np * 2],     ah[mf], bl0, bl1);
                        mma16816(c[mf][np * 2 + 1], ah[mf], bl2, bl3);
                        mma16816(c[mf][np * 2],     al[mf], bh0, bh1);
                        mma16816(c[mf][np * 2 + 1], al[mf], bh2, bh3);
                    }
                }
            }
        }
    }

    // ---- bias + SCALE + bf16 split store to g_qh/g_ql [pixel][c] ----
#pragma unroll
    for (int mf = 0; mf < 2; mf++) {
        int r0 = warpM * 32 + mf * 16 + (lane >> 2);
#pragma unroll
        for (int half = 0; half < 2; half++) {
            int r = r0 + half * 8;
            int gy = blockIdx.y * 8 + (r >> 4);
            int gx = blockIdx.x * 16 + (r & 15);
            size_t pofs = (size_t)(gy * 128 + gx) * 128;
#pragma unroll
            for (int nf = 0; nf < 4; nf++) {
                int n = warpN * 32 + nf * 8 + 2 * (lane & 3);
                float v0 = (c[mf][nf][half * 2]     + sbias[n])     * SCALE;
                float v1 = (c[mf][nf][half * 2 + 1] + sbias[n + 1]) * SCALE;
                uint32_t hw, lw;
                split2(v0, v1, hw, lw);
                *(uint32_t*)(g_qh + pofs + n) = hw;
                *(uint32_t*)(g_ql + pofs + n) = lw;
            }
        }
    }
}

// ---------------------------------------------------------------------------
// Kernel 2: k path (RMSNorm + kproj -> bf16 split planes) + V split/transpose
// to [pixel][c] planes. (unchanged)
// ---------------------------------------------------------------------------
__global__ __launch_bounds__(256)
void kprep_kernel(const float* __restrict__ kin, const float* __restrict__ vin,
                  const float* __restrict__ kb) {
    extern __shared__ float sm2[];
    float* ksh  = sm2;                 // 16*129 = 2064
    float* wbuf = sm2 + 2064;          // 8192
    float* rstd = sm2 + 2064 + 8192;   // 16
    const int tid = threadIdx.x;
    const int tx = tid & 15;
    const int ty = tid >> 4;
    const int pbase = blockIdx.x * 16;

    for (int idx = tid; idx < 2048; idx += 256) {
        int c = idx >> 4, pp = idx & 15;
        ksh[pp * 129 + c] = kin[c * 1024 + pbase + pp];
    }
    __syncthreads();
    if (tid < 16) {
        float ss = 0.f;
        const float* row = ksh + tid * 129;
        for (int c = 0; c < 128; c++) { float v = row[c]; ss += v * v; }
        rstd[tid] = rsqrtf(ss * (1.0f / 128.0f) + EPS);
    }
    float pacc[8];
#pragma unroll
    for (int o = 0; o < 8; o++) pacc[o] = 0.f;
    const int rofs = ty * 129;
    for (int ch = 0; ch < 2; ch++) {
        __syncthreads();
        const float4* src = (const float4*)(g_wkt + ch * 64 * 128);
        float4* dst = (float4*)wbuf;
        for (int j = tid; j < 2048; j += 256) dst[j] = src[j];
        __syncthreads();
#pragma unroll 2
        for (int cl = 0; cl < 64; cl++) {
            float in0 = ksh[rofs + ch * 64 + cl];
            const float* wrow = wbuf + cl * 128 + tx * 8;
            float4 w0 = *(const float4*)wrow;
            float4 w1 = *(const float4*)(wrow + 4);
            pacc[0] += in0 * w0.x; pacc[1] += in0 * w0.y;
            pacc[2] += in0 * w0.z; pacc[3] += in0 * w0.w;
            pacc[4] += in0 * w1.x; pacc[5] += in0 * w1.y;
            pacc[6] += in0 * w1.z; pacc[7] += in0 * w1.w;
        }
    }
    {
        float r = rstd[ty];
        size_t pofs = (size_t)(pbase + ty) * 128 + tx * 8;
#pragma unroll
        for (int j = 0; j < 4; j++) {
            uint32_t hw, lw;
            split2(pacc[2 * j] * r + kb[tx * 8 + 2 * j],
                   pacc[2 * j + 1] * r + kb[tx * 8 + 2 * j + 1], hw, lw);
            *(uint32_t*)(g_kh + pofs + 2 * j) = hw;
            *(uint32_t*)(g_kl + pofs + 2 * j) = lw;
        }
    }
    __syncthreads();
    for (int idx = tid; idx < 2048; idx += 256) {
        int c = idx >> 4, pp = idx & 15;
        ksh[pp * 129 + c] = vin[c * 1024 + pbase + pp];
    }
    __syncthreads();
    for (int idx = tid; idx < 2048; idx += 256) {
        int pp = idx >> 7, c = idx & 127;
        unsigned short h, l;
        split1(ksh[pp * 129 + c], h, l);
        g_vh[(size_t)(pbase + pp) * 128 + c] = h;
        g_vl[(size_t)(pbase + pp) * 128 + c] = l;
    }
}

// ---------------------------------------------------------------------------
// Kernel 3: NATTEN attention via mma.sync. 512 threads: logits on 16 warps
// (h x key-quarter), softmax/AV keep validated 256-thread/8-warp mappings.
// smem layout unchanged (97280 B), 2 blocks/SM -> 32 warps/SM.
// ---------------------------------------------------------------------------
__global__ __launch_bounds__(512, 2)
void attn_kernel(float* __restrict__ out) {
    extern __shared__ char sma[];
    const int OF_KH = 0, OF_KL = 17408, OF_VH = 34816, OF_VL = 52224;
    const int OF_QH = 69632, OF_QL = 73984, OF_LG = 78336, OF_AMH = 92672, OF_AML = 94976;

    const uint32_t sb = smem_u32(sma);
    float* lg = (float*)(sma + OF_LG);
    const int tid = threadIdx.x;
    const int lane = tid & 31, wid = tid >> 5;
    const int arow = lane & 15, khalf = lane >> 4;
    const int bn_off = (lane & 7) | ((lane >> 1) & 8);
    const int bk_half = (lane >> 3) & 1;

    const int bx = blockIdx.x, by = blockIdx.y;
    const int ks_h = min(max(by - 3, 0), 25);
    const int ks_w = min(max(bx - 3, 0), 25);

    // ---- zero-fill V pad rows (kk 49..63) ----
    for (int idx = tid; idx < 480; idx += 512) {
        int p = idx / 240, r = idx - p * 240;
        int kk = 49 + (r >> 4), g = r & 15;
        *(uint4*)(sma + OF_VH + p * 17408 + kk * 272 + g * 16) = make_uint4(0u, 0u, 0u, 0u);
    }
    // ---- cp.async stage K/V valid rows [kk][c] from [pixel][c] planes ----
    for (int idx = tid; idx < 3136; idx += 512) {
        int g = idx & 15;
        int t = idx >> 4;
        int kk = t % 49;
        int sp = t / 49;
        int sel = sp >> 1, p = sp & 1;
        int m = kk / 7, n = kk - m * 7;
        size_t pix = (size_t)((ks_h + m) * 32 + ks_w + n);
        const unsigned short* srcp = sel ? (p ? g_vl : g_vh) : (p ? g_kl : g_kh);
        cp16(sb + sel * 34816 + p * 17408 + kk * 272 + g * 16, srcp + pix * 128 + g * 8);
    }
    // ---- cp.async stage Q [q][c] (already scaled) ----
    for (int idx = tid; idx < 512; idx += 512) {
        int p = idx >> 8, r = idx & 255;
        int q = r >> 4, g = r & 15;
        int gi = by * 4 + (q >> 2), gj = bx * 4 + (q & 3);
        cp16(sb + (p ? OF_QL : OF_QH) + q * 272 + g * 16,
             (p ? g_ql : g_qh) + (size_t)(gi * 128 + gj) * 128 + g * 8);
    }
    CP_COMMIT();
    CP_WAIT0();
    __syncthreads();

    // ---- logits: 16 warps = (head h, key-quarter nh), warp tile m16 x n16 ----
    {
        const int h = wid & 3, nh = wid >> 2;     // nh 0..3
        float cl4[2][4];
#pragma unroll
        for (int t = 0; t < 2; t++)
#pragma unroll
            for (int j = 0; j < 4; j++) cl4[t][j] = 0.f;

        const uint32_t qbase = sb + OF_QH + arow * 272;
#pragma unroll
        for (int ks = 0; ks < 2; ks++) {
            const int acol = (h * 32 + ks * 16 + khalf * 8) * 2;
            uint32_t ah[4], al[4];
            ldsm4(ah[0], ah[1], ah[2], ah[3], qbase + acol);
            ldsm4(al[0], al[1], al[2], al[3], qbase + (OF_QL - OF_QH) + acol);
            const uint32_t baddr = sb + OF_KH + (nh * 16 + bn_off) * 272
                                 + (h * 32 + ks * 16 + bk_half * 8) * 2;
            uint32_t bh0, bh1, bh2, bh3, bl0, bl1, bl2, bl3;
            ldsm4(bh0, bh1, bh2, bh3, baddr);
            ldsm4(bl0, bl1, bl2, bl3, baddr + (OF_KL - OF_KH));
            mma16816(cl4[0], ah, bh0, bh1);
            mma16816(cl4[1], ah, bh2, bh3);
            mma16816(cl4[0], ah, bl0, bl1);
            mma16816(cl4[1], ah, bl2, bl3);
            mma16816(cl4[0], al, bh0, bh1);
            mma16816(cl4[1], al, bh2, bh3);
        }
        const int q0 = lane >> 2;
#pragma unroll
        for (int t8 = 0; t8 < 2; t8++) {
            int kk0 = nh * 16 + t8 * 8 + 2 * (lane & 3);
            if (kk0 < 56) {
                lg[q0 * 224 + h * 56 + kk0]           = cl4[t8][0];
                lg[q0 * 224 + h * 56 + kk0 + 1]       = cl4[t8][1];
                lg[(q0 + 8) * 224 + h * 56 + kk0]     = cl4[t8][2];
                lg[(q0 + 8) * 224 + h * 56 + kk0 + 1] = cl4[t8][3];
            }
        }
    }
    __syncthreads();

    // ---- fused softmax + head-mean, register-resident (threads 0..255) ----
    if (tid < 256) {
        const int q = tid >> 4, h = (tid >> 2) & 3, sub = tid & 3;
        const float* base = lg + q * 224 + h * 56;
        float pv[13];
        float mx = -1e30f;
#pragma unroll
        for (int j = 0; j < 13; j++) {
            int kk = sub + 4 * j;
            pv[j] = (kk < 49) ? base[kk] : -1e30f;
            mx = fmaxf(mx, pv[j]);
        }
        mx = fmaxf(mx, __shfl_xor_sync(0xffffffffu, mx, 1));
        mx = fmaxf(mx, __shfl_xor_sync(0xffffffffu, mx, 2));
        float s = 0.f;
#pragma unroll
        for (int j = 0; j < 13; j++) {
            pv[j] = __expf(pv[j] - mx);
            s += pv[j];
        }
        s += __shfl_xor_sync(0xffffffffu, s, 1);
        s += __shfl_xor_sync(0xffffffffu, s, 2);
        const float inv = 0.25f / s;
#pragma unroll
        for (int j = 0; j < 13; j++) {
            float a = pv[j] * inv;
            a += __shfl_xor_sync(0xffffffffu, a, 4);
            a += __shfl_xor_sync(0xffffffffu, a, 8);
            pv[j] = a;
        }
        if (h == 0) {
#pragma unroll
            for (int j = 0; j < 13; j++) {
                int kk = sub + 4 * j;
                if (kk < 49) {
                    unsigned short hh, ll;
                    split1(pv[j], hh, ll);
                    *(unsigned short*)(sma + OF_AMH + q * 144 + kk * 2) = hh;
                    *(unsigned short*)(sma + OF_AML + q * 144 + kk * 2) = ll;
                }
            }
        } else if (h == 1) {
            for (int kk = 49 + sub; kk < 64; kk += 4) {
                *(unsigned short*)(sma + OF_AMH + q * 144 + kk * 2) = 0;
                *(unsigned short*)(sma + OF_AML + q * 144 + kk * 2) = 0;
            }
        }
    }
    __syncthreads();

    // ---- AV: 8 warps (wid<8), warp = 16 channels, K=64; B via ldmatrix.trans ----
    if (wid < 8) {
        float co[2][4];
#pragma unroll
        for (int t = 0; t < 2; t++)
#pragma unroll
            for (int j = 0; j < 4; j++) co[t][j] = 0.f;

#pragma unroll
        for (int ks = 0; ks < 4; ks++) {
            const uint32_t aaddr = sb + OF_AMH + arow * 144 + (ks * 16 + khalf * 8) * 2;
            uint32_t ah[4], al[4];
            ldsm4(ah[0], ah[1], ah[2], ah[3], aaddr);
            ldsm4(al[0], al[1], al[2], al[3], aaddr + (OF_AML - OF_AMH));
            const uint32_t baddr = sb + OF_VH + (ks * 16 + arow) * 272
                                 + (wid * 16 + khalf * 8) * 2;
            uint32_t bh0, bh1, bh2, bh3, bl0, bl1, bl2, bl3;
            ldsm4t(bh0, bh1, bh2, bh3, baddr);
            ldsm4t(bl0, bl1, bl2, bl3, baddr + (OF_VL - OF_VH));
            mma16816(co[0], ah, bh0, bh1);
            mma16816(co[1], ah, bh2, bh3);
            mma16816(co[0], ah, bl0, bl1);
            mma16816(co[1], ah, bl2, bl3);
            mma16816(co[0], al, bh0, bh1);
            mma16816(co[1], al, bh2, bh3);
        }

        const int q0 = lane >> 2;
        const int pix0 = (by * 4 + (q0 >> 2)) * 128 + bx * 4 + (q0 & 3);
        const int q1 = q0 + 8;
        const int pix1 = (by * 4 + (q1 >> 2)) * 128 + bx * 4 + (q1 & 3);
#pragma unroll
        for (int t8 = 0; t8 < 2; t8++) {
            int cch = wid * 16 + t8 * 8 + 2 * (lane & 3);
            out[cch * 16384 + pix0]       = co[t8][0];
            out[(cch + 1) * 16384 + pix0] = co[t8][1];
            out[cch * 16384 + pix1]       = co[t8][2];
            out[(cch + 1) * 16384 + pix1] = co[t8][3];
        }
    }
}

// ---------------------------------------------------------------------------
extern "C" void kernel_launch(void* const* d_in, const int* in_sizes, int n_in,
                              void* d_out, int out_size) {
    const float* q  = (const float*)d_in[0];
    const float* k  = (const float*)d_in[1];
    const float* v  = (const float*)d_in[2];
    const float* cw = (const float*)d_in[3];
    const float* nq = (const float*)d_in[4];
    const float* nk = (const float*)d_in[5];
    const float* qw = (const float*)d_in[6];
    const float* qb = (const float*)d_in[7];
    const float* kw = (const float*)d_in[8];
    const float* kb = (const float*)d_in[9];
    float* out = (float*)d_out;

    cudaFuncSetAttribute(convq_mma, cudaFuncAttributeMaxDynamicSharedMemorySize, 174720);
    cudaFuncSetAttribute(attn_kernel, cudaFuncAttributeMaxDynamicSharedMemorySize, 97280);

    prep_kernel<<<576, 256>>>(cw, nq, nk, qw, kw);
    convq_mma<<<dim3(8, 16), 512, 174720>>>(q, qb);
    kprep_kernel<<<64, 256, 41088>>>(k, v, kb);
    attn_kernel<<<dim3(32, 32), 512, 97280>>>(out);
}

// round 17
// speedup vs baseline: 1.0213x; 1.0213x over previous
#include <cuda_runtime.h>
#include <cuda_bf16.h>
#include <cstdint>

#define EPS   1.1920928955078125e-07f
#define SCALE 0.17677669529663687f   // 1/sqrt(32)

// ---------------------------------------------------------------------------
// scratch (static __device__ — no allocations allowed)
// ---------------------------------------------------------------------------
__device__ __align__(16) unsigned short g_cwp[36 * 9216];  // conv W bf16 [tap][ch][hi/lo] planes
__device__ __align__(16) unsigned short g_wqp[4 * 9216];   // qproj W bf16 planes
__device__ __align__(16) float g_wkt[128 * 128];           // kproj_w^T * normk_w
__device__ __align__(16) unsigned short g_qh[16384 * 128]; // q bf16 hi, [pixel][c], pre-scaled by SCALE
__device__ __align__(16) unsigned short g_ql[16384 * 128]; // q bf16 lo
__device__ __align__(16) unsigned short g_kh[1024 * 128];  // k bf16 hi, [pixel][c]
__device__ __align__(16) unsigned short g_kl[1024 * 128];
__device__ __align__(16) unsigned short g_vh[1024 * 128];  // v bf16 hi, [pixel][c]
__device__ __align__(16) unsigned short g_vl[1024 * 128];

// ---------------------------------------------------------------------------
// helpers
// ---------------------------------------------------------------------------
__device__ __forceinline__ uint32_t smem_u32(const void* p) {
    uint32_t a;
    asm("{ .reg .u64 t; cvta.to.shared.u64 t, %1; cvt.u32.u64 %0, t; }" : "=r"(a) : "l"(p));
    return a;
}
__device__ __forceinline__ void ldsm4(uint32_t& r0, uint32_t& r1, uint32_t& r2, uint32_t& r3,
                                      uint32_t addr) {
    asm volatile("ldmatrix.sync.aligned.m8n8.x4.shared.b16 {%0,%1,%2,%3}, [%4];"
                 : "=r"(r0), "=r"(r1), "=r"(r2), "=r"(r3) : "r"(addr));
}
__device__ __forceinline__ void ldsm4t(uint32_t& r0, uint32_t& r1, uint32_t& r2, uint32_t& r3,
                                       uint32_t addr) {
    asm volatile("ldmatrix.sync.aligned.m8n8.x4.trans.shared.b16 {%0,%1,%2,%3}, [%4];"
                 : "=r"(r0), "=r"(r1), "=r"(r2), "=r"(r3) : "r"(addr));
}
__device__ __forceinline__ void mma16816(float* c, const uint32_t* a, uint32_t b0, uint32_t b1) {
    asm volatile("mma.sync.aligned.m16n8k16.row.col.f32.bf16.bf16.f32 "
                 "{%0,%1,%2,%3}, {%4,%5,%6,%7}, {%8,%9}, {%0,%1,%2,%3};"
                 : "+f"(c[0]), "+f"(c[1]), "+f"(c[2]), "+f"(c[3])
                 : "r"(a[0]), "r"(a[1]), "r"(a[2]), "r"(a[3]), "r"(b0), "r"(b1));
}
__device__ __forceinline__ void cp16(uint32_t dst, const void* src) {
    asm volatile("cp.async.cg.shared.global [%0], [%1], 16;" :: "r"(dst), "l"(src));
}
#define CP_COMMIT() asm volatile("cp.async.commit_group;" ::: "memory")
#define CP_WAIT0()  asm volatile("cp.async.wait_group 0;" ::: "memory")

__device__ __forceinline__ void split2(float v0, float v1, uint32_t& hw, uint32_t& lw) {
    __nv_bfloat16 h0 = __float2bfloat16(v0), h1 = __float2bfloat16(v1);
    float r0 = v0 - __bfloat162float(h0), r1 = v1 - __bfloat162float(h1);
    __nv_bfloat16 l0 = __float2bfloat16(r0), l1 = __float2bfloat16(r1);
    hw = (uint32_t)__bfloat16_as_ushort(h0) | ((uint32_t)__bfloat16_as_ushort(h1) << 16);
    lw = (uint32_t)__bfloat16_as_ushort(l0) | ((uint32_t)__bfloat16_as_ushort(l1) << 16);
}
__device__ __forceinline__ void split1(float v, unsigned short& h, unsigned short& l) {
    __nv_bfloat16 hb = __float2bfloat16(v);
    __nv_bfloat16 lb = __float2bfloat16(v - __bfloat162float(hb));
    h = __bfloat16_as_ushort(hb);
    l = __bfloat16_as_ushort(lb);
}

// ---------------------------------------------------------------------------
// Kernel 0: weight prep (unchanged)
// ---------------------------------------------------------------------------
__global__ void prep_kernel(const float* __restrict__ conv_w,
                            const float* __restrict__ normq,
                            const float* __restrict__ normk,
                            const float* __restrict__ qw,
                            const float* __restrict__ kw) {
    int idx = blockIdx.x * 256 + threadIdx.x;
    if (idx < 147456) {
        int oc = idx & 127;
        int ci = (idx >> 7) & 127;
        int tap = idx >> 14;
        float w = conv_w[(oc * 128 + ci) * 9 + tap];
        __nv_bfloat16 h = __float2bfloat16(w);
        __nv_bfloat16 l = __float2bfloat16(w - __bfloat162float(h));
        int ch = ci >> 6, cl = ci & 63;
        size_t base = (size_t)((tap * 2 + ch) * 2) * 9216;
        g_cwp[base + oc * 72 + cl]        = __bfloat16_as_ushort(h);
        g_cwp[base + 9216 + oc * 72 + cl] = __bfloat16_as_ushort(l);
    }
    if (idx < 16384) {
        int o = idx & 127;
        int c = idx >> 7;
        g_wkt[idx] = kw[o * 128 + c] * normk[c];
        float v = qw[o * 128 + c] * normq[c];
        __nv_bfloat16 h = __float2bfloat16(v);
        __nv_bfloat16 l = __float2bfloat16(v - __bfloat162float(h));
        int ch = c >> 6, cl = c & 63;
        size_t base = (size_t)(ch * 2) * 9216;
        g_wqp[base + o * 72 + cl]        = __bfloat16_as_ushort(h);
        g_wqp[base + 9216 + o * 72 + cl] = __bfloat16_as_ushort(l);
    }
}

// ---------------------------------------------------------------------------
// Kernel 1: conv3x3 + RMSNorm + qproj via mma.sync (R13 winner: 256 threads,
// 4M x 2N warps, cp.async double-buffered weight staging).
// ---------------------------------------------------------------------------
__global__ __launch_bounds__(256, 1)
void convq_mma(const float* __restrict__ qin, const float* __restrict__ qb) {
    extern __shared__ char smc[];
    const int OF_PL = 48960;
    const int OF_B0 = 97920;
    const int OF_B1 = 134784;
    const int OF_SSQ  = 171648;
    const int OF_RSTD = 172672;
    const int OF_BIAS = 173184;
    const int OF_CH = 0, OF_CL = 34816;

    const uint32_t sb = smem_u32(smc);
    const int tid = threadIdx.x;
    const int lane = tid & 31, wid = tid >> 5;
    const int warpM = wid & 3, warpN = wid >> 2;
    const int arow = lane & 15, khalf = lane >> 4;
    const int bn_off = (lane & 7) | ((lane >> 1) & 8);
    const int bk_half = (lane >> 3) & 1;

    float* sbias = (float*)(smc + OF_BIAS);
    if (tid < 128) sbias[tid] = qb[tid];

    {
        const char* src = (const char*)g_cwp;
        for (int j = tid; j < 2304; j += 256) cp16(sb + OF_B0 + j * 16, src + j * 16);
        CP_COMMIT();
    }

    {
        unsigned short* ph = (unsigned short*)smc;
        unsigned short* pl = (unsigned short*)(smc + OF_PL);
        const int gy0 = blockIdx.y * 8 - 1, gx0 = blockIdx.x * 16 - 1;
        for (int idx = tid; idx < 23040; idx += 256) {
            int ci = idx / 180, pix = idx - ci * 180;
            int py = pix / 18, px = pix - py * 18;
            int gy = gy0 + py, gx = gx0 + px;
            float x = 0.f;
            if ((unsigned)gy < 128u && (unsigned)gx < 128u) x = qin[ci * 16384 + gy * 128 + gx];
            unsigned short h, l;
            split1(x, h, l);
            ph[pix * 136 + ci] = h;
            pl[pix * 136 + ci] = l;
        }
    }

    int rowq[2], colq[2];
#pragma unroll
    for (int mf = 0; mf < 2; mf++) {
        int r = warpM * 32 + mf * 16 + arow;
        rowq[mf] = r >> 4;
        colq[mf] = r & 15;
    }

    float c[2][8][4];
#pragma unroll
    for (int mf = 0; mf < 2; mf++)
#pragma unroll
        for (int nf = 0; nf < 8; nf++)
#pragma unroll
            for (int j = 0; j < 4; j++) c[mf][nf][j] = 0.f;

    for (int i = 0; i < 18; i++) {
        CP_WAIT0();
        __syncthreads();
        if (i < 17) {
            const char* src = (const char*)g_cwp + (size_t)(i + 1) * 36864;
            const uint32_t dstb = sb + (((i + 1) & 1) ? OF_B1 : OF_B0);
            for (int j = tid; j < 2304; j += 256) cp16(dstb + j * 16, src + j * 16);
            CP_COMMIT();
        }
        const int tap = i >> 1, ch = i & 1;
        const int dy = tap / 3, dx = tap - dy * 3;
        const uint32_t Bh = sb + ((i & 1) ? OF_B1 : OF_B0);
        const uint32_t Bl = Bh + 18432;

        uint32_t apix[2];
#pragma unroll
        for (int mf = 0; mf < 2; mf++)
            apix[mf] = sb + ((rowq[mf] + dy) * 18 + colq[mf] + dx) * 272;

#pragma unroll
        for (int ks = 0; ks < 4; ks++) {
            const int acol2 = (ch * 64 + ks * 16 + khalf * 8) * 2;
            uint32_t ah[2][4], al[2][4];
            ldsm4(ah[0][0], ah[0][1], ah[0][2], ah[0][3], apix[0] + acol2);
            ldsm4(ah[1][0], ah[1][1], ah[1][2], ah[1][3], apix[1] + acol2);
            ldsm4(al[0][0], al[0][1], al[0][2], al[0][3], apix[0] + OF_PL + acol2);
            ldsm4(al[1][0], al[1][1], al[1][2], al[1][3], apix[1] + OF_PL + acol2);
            const int bofs = (warpN * 64 + bn_off) * 144 + (ks * 16 + bk_half * 8) * 2;
#pragma unroll
            for (int np = 0; np < 4; np++) {
                uint32_t bh0, bh1, bh2, bh3, bl0, bl1, bl2, bl3;
                ldsm4(bh0, bh1, bh2, bh3, Bh + bofs + np * 16 * 144);
                ldsm4(bl0, bl1, bl2, bl3, Bl + bofs + np * 16 * 144);
#pragma unroll
                for (int mf = 0; mf < 2; mf++) {
                    mma16816(c[mf][np * 2],     ah[mf], bh0, bh1);
                    mma16816(c[mf][np * 2 + 1], ah[mf], bh2, bh3);
                    mma16816(c[mf][np * 2],     ah[mf], bl0, bl1);
                    mma16816(c[mf][np * 2 + 1], ah[mf], bl2, bl3);
                    mma16816(c[mf][np * 2],     al[mf], bh0, bh1);
                    mma16816(c[mf][np * 2 + 1], al[mf], bh2, bh3);
                }
            }
        }
    }

    float s[2][2];
#pragma unroll
    for (int mf = 0; mf < 2; mf++) { s[mf][0] = 0.f; s[mf][1] = 0.f; }
#pragma unroll
    for (int mf = 0; mf < 2; mf++)
#pragma unroll
        for (int nf = 0; nf < 8; nf++) {
            s[mf][0] += c[mf][nf][0] * c[mf][nf][0] + c[mf][nf][1] * c[mf][nf][1];
            s[mf][1] += c[mf][nf][2] * c[mf][nf][2] + c[mf][nf][3] * c[mf][nf][3];
        }
#pragma unroll
    for (int off = 1; off <= 2; off <<= 1) {
#pragma unroll
        for (int mf = 0; mf < 2; mf++) {
            s[mf][0] += __shfl_xor_sync(0xffffffffu, s[mf][0], off);
            s[mf][1] += __shfl_xor_sync(0xffffffffu, s[mf][1], off);
        }
    }
    __syncthreads();

    {
        const char* src = (const char*)g_wqp;
        for (int j = tid; j < 4608; j += 256) cp16(sb + OF_B0 + j * 16, src + j * 16);
        CP_COMMIT();
    }

    float* ssq2 = (float*)(smc + OF_SSQ);
    if ((lane & 3) == 0) {
#pragma unroll
        for (int mf = 0; mf < 2; mf++) {
            int r = warpM * 32 + mf * 16 + (lane >> 2);
            ssq2[warpN * 128 + r]     = s[mf][0];
            ssq2[warpN * 128 + r + 8] = s[mf][1];
        }
    }
    __syncthreads();
    float* rstd = (float*)(smc + OF_RSTD);
    if (tid < 128)
        rstd[tid] = rsqrtf((ssq2[tid] + ssq2[128 + tid]) * (1.0f / 128.0f) + EPS);
    __syncthreads();

#pragma unroll
    for (int mf = 0; mf < 2; mf++) {
        int r0 = warpM * 32 + mf * 16 + (lane >> 2);
        int r1 = r0 + 8;
        float s0 = rstd[r0], s1 = rstd[r1];
#pragma unroll
        for (int nf = 0; nf < 8; nf++) {
            int n = warpN * 64 + nf * 8 + 2 * (lane & 3);
            uint32_t hw, lw;
            split2(c[mf][nf][0] * s0, c[mf][nf][1] * s0, hw, lw);
            *(uint32_t*)(smc + OF_CH + r0 * 272 + n * 2) = hw;
            *(uint32_t*)(smc + OF_CL + r0 * 272 + n * 2) = lw;
            split2(c[mf][nf][2] * s1, c[mf][nf][3] * s1, hw, lw);
            *(uint32_t*)(smc + OF_CH + r1 * 272 + n * 2) = hw;
            *(uint32_t*)(smc + OF_CL + r1 * 272 + n * 2) = lw;
        }
    }
#pragma unroll
    for (int mf = 0; mf < 2; mf++)
#pragma unroll
        for (int nf = 0; nf < 8; nf++)
#pragma unroll
            for (int j = 0; j < 4; j++) c[mf][nf][j] = 0.f;
    CP_WAIT0();
    __syncthreads();

    {
        uint32_t arowaddr[2];
#pragma unroll
        for (int mf = 0; mf < 2; mf++)
            arowaddr[mf] = sb + (warpM * 32 + mf * 16 + arow) * 272;
#pragma unroll
        for (int ch = 0; ch < 2; ch++) {
            const uint32_t Bh = sb + OF_B0 + ch * 2 * 18432;
            const uint32_t Bl = Bh + 18432;
#pragma unroll
            for (int ks = 0; ks < 4; ks++) {
                const int acol2 = (ch * 64 + ks * 16 + khalf * 8) * 2;
                uint32_t ah[2][4], al[2][4];
                ldsm4(ah[0][0], ah[0][1], ah[0][2], ah[0][3], arowaddr[0] + OF_CH + acol2);
                ldsm4(ah[1][0], ah[1][1], ah[1][2], ah[1][3], arowaddr[1] + OF_CH + acol2);
                ldsm4(al[0][0], al[0][1], al[0][2], al[0][3], arowaddr[0] + OF_CL + acol2);
                ldsm4(al[1][0], al[1][1], al[1][2], al[1][3], arowaddr[1] + OF_CL + acol2);
                const int bofs = (warpN * 64 + bn_off) * 144 + (ks * 16 + bk_half * 8) * 2;
#pragma unroll
                for (int np = 0; np < 4; np++) {
                    uint32_t bh0, bh1, bh2, bh3, bl0, bl1, bl2, bl3;
                    ldsm4(bh0, bh1, bh2, bh3, Bh + bofs + np * 16 * 144);
                    ldsm4(bl0, bl1, bl2, bl3, Bl + bofs + np * 16 * 144);
#pragma unroll
                    for (int mf = 0; mf < 2; mf++) {
                        mma16816(c[mf][np * 2],     ah[mf], bh0, bh1);
                        mma16816(c[mf][np * 2 + 1], ah[mf], bh2, bh3);
                        mma16816(c[mf][np * 2],     ah[mf], bl0, bl1);
                        mma16816(c[mf][np * 2 + 1], ah[mf], bl2, bl3);
                        mma16816(c[mf][np * 2],     al[mf], bh0, bh1);
                        mma16816(c[mf][np * 2 + 1], al[mf], bh2, bh3);
                    }
                }
            }
        }
    }

#pragma unroll
    for (int mf = 0; mf < 2; mf++) {
        int r0 = warpM * 32 + mf * 16 + (lane >> 2);
#pragma unroll
        for (int half = 0; half < 2; half++) {
            int r = r0 + half * 8;
            int gy = blockIdx.y * 8 + (r >> 4);
            int gx = blockIdx.x * 16 + (r & 15);
            size_t pofs = (size_t)(gy * 128 + gx) * 128;
#pragma unroll
            for (int nf = 0; nf < 8; nf++) {
                int n = warpN * 64 + nf * 8 + 2 * (lane & 3);
                float v0 = (c[mf][nf][half * 2]     + sbias[n])     * SCALE;
                float v1 = (c[mf][nf][half * 2 + 1] + sbias[n + 1]) * SCALE;
                uint32_t hw, lw;
                split2(v0, v1, hw, lw);
                *(uint32_t*)(g_qh + pofs + n) = hw;
                *(uint32_t*)(g_ql + pofs + n) = lw;
            }
        }
    }
}

// ---------------------------------------------------------------------------
// Kernel 2: k path (RMSNorm + kproj -> bf16 split planes) + V split/transpose
// to [pixel][c] planes. (R13 version)
// ---------------------------------------------------------------------------
__global__ __launch_bounds__(256)
void kprep_kernel(const float* __restrict__ kin, const float* __restrict__ vin,
                  const float* __restrict__ kb) {
    extern __shared__ float sm2[];
    float* ksh  = sm2;                 // 16*129 = 2064
    float* wbuf = sm2 + 2064;          // 8192
    float* rstd = sm2 + 2064 + 8192;   // 16
    const int tid = threadIdx.x;
    const int tx = tid & 15;
    const int ty = tid >> 4;
    const int pbase = blockIdx.x * 16;

    for (int idx = tid; idx < 2048; idx += 256) {
        int c = idx >> 4, pp = idx & 15;
        ksh[pp * 129 + c] = kin[c * 1024 + pbase + pp];
    }
    __syncthreads();
    if (tid < 16) {
        float ss = 0.f;
        const float* row = ksh + tid * 129;
        for (int c = 0; c < 128; c++) { float v = row[c]; ss += v * v; }
        rstd[tid] = rsqrtf(ss * (1.0f / 128.0f) + EPS);
    }
    float pacc[8];
#pragma unroll
    for (int o = 0; o < 8; o++) pacc[o] = 0.f;
    const int rofs = ty * 129;
    for (int ch = 0; ch < 2; ch++) {
        __syncthreads();
        const float4* src = (const float4*)(g_wkt + ch * 64 * 128);
        float4* dst = (float4*)wbuf;
        for (int j = tid; j < 2048; j += 256) dst[j] = src[j];
        __syncthreads();
#pragma unroll 2
        for (int cl = 0; cl < 64; cl++) {
            float in0 = ksh[rofs + ch * 64 + cl];
            const float* wrow = wbuf + cl * 128 + tx * 8;
            float4 w0 = *(const float4*)wrow;
            float4 w1 = *(const float4*)(wrow + 4);
            pacc[0] += in0 * w0.x; pacc[1] += in0 * w0.y;
            pacc[2] += in0 * w0.z; pacc[3] += in0 * w0.w;
            pacc[4] += in0 * w1.x; pacc[5] += in0 * w1.y;
            pacc[6] += in0 * w1.z; pacc[7] += in0 * w1.w;
        }
    }
    {
        float r = rstd[ty];
        size_t pofs = (size_t)(pbase + ty) * 128 + tx * 8;
#pragma unroll
        for (int j = 0; j < 4; j++) {
            uint32_t hw, lw;
            split2(pacc[2 * j] * r + kb[tx * 8 + 2 * j],
                   pacc[2 * j + 1] * r + kb[tx * 8 + 2 * j + 1], hw, lw);
            *(uint32_t*)(g_kh + pofs + 2 * j) = hw;
            *(uint32_t*)(g_kl + pofs + 2 * j) = lw;
        }
    }
    __syncthreads();
    for (int idx = tid; idx < 2048; idx += 256) {
        int c = idx >> 4, pp = idx & 15;
        ksh[pp * 129 + c] = vin[c * 1024 + pbase + pp];
    }
    __syncthreads();
    for (int idx = tid; idx < 2048; idx += 256) {
        int pp = idx >> 7, c = idx & 127;
        unsigned short h, l;
        split1(ksh[pp * 129 + c], h, l);
        g_vh[(size_t)(pbase + pp) * 128 + c] = h;
        g_vl[(size_t)(pbase + pp) * 128 + c] = l;
    }
}

// ---------------------------------------------------------------------------
// Kernel 3: NATTEN attention via mma.sync (R16 512-thread version, measured
// 24.06us / occ 42.6%). smem 97280 B, 2 blocks/SM.
// ---------------------------------------------------------------------------
__global__ __launch_bounds__(512, 2)
void attn_kernel(float* __restrict__ out) {
    extern __shared__ char sma[];
    const int OF_KH = 0, OF_KL = 17408, OF_VH = 34816, OF_VL = 52224;
    const int OF_QH = 69632, OF_QL = 73984, OF_LG = 78336, OF_AMH = 92672, OF_AML = 94976;

    const uint32_t sb = smem_u32(sma);
    float* lg = (float*)(sma + OF_LG);
    const int tid = threadIdx.x;
    const int lane = tid & 31, wid = tid >> 5;
    const int arow = lane & 15, khalf = lane >> 4;
    const int bn_off = (lane & 7) | ((lane >> 1) & 8);
    const int bk_half = (lane >> 3) & 1;

    const int bx = blockIdx.x, by = blockIdx.y;
    const int ks_h = min(max(by - 3, 0), 25);
    const int ks_w = min(max(bx - 3, 0), 25);

    // ---- zero-fill V pad rows (kk 49..63) ----
    for (int idx = tid; idx < 480; idx += 512) {
        int p = idx / 240, r = idx - p * 240;
        int kk = 49 + (r >> 4), g = r & 15;
        *(uint4*)(sma + OF_VH + p * 17408 + kk * 272 + g * 16) = make_uint4(0u, 0u, 0u, 0u);
    }
    // ---- cp.async stage K/V valid rows [kk][c] from [pixel][c] planes ----
    for (int idx = tid; idx < 3136; idx += 512) {
        int g = idx & 15;
        int t = idx >> 4;
        int kk = t % 49;
        int sp = t / 49;
        int sel = sp >> 1, p = sp & 1;
        int m = kk / 7, n = kk - m * 7;
        size_t pix = (size_t)((ks_h + m) * 32 + ks_w + n);
        const unsigned short* srcp = sel ? (p ? g_vl : g_vh) : (p ? g_kl : g_kh);
        cp16(sb + sel * 34816 + p * 17408 + kk * 272 + g * 16, srcp + pix * 128 + g * 8);
    }
    // ---- cp.async stage Q [q][c] (already scaled) ----
    for (int idx = tid; idx < 512; idx += 512) {
        int p = idx >> 8, r = idx & 255;
        int q = r >> 4, g = r & 15;
        int gi = by * 4 + (q >> 2), gj = bx * 4 + (q & 3);
        cp16(sb + (p ? OF_QL : OF_QH) + q * 272 + g * 16,
             (p ? g_ql : g_qh) + (size_t)(gi * 128 + gj) * 128 + g * 8);
    }
    CP_COMMIT();
    CP_WAIT0();
    __syncthreads();

    // ---- logits: 16 warps = (head h, key-quarter nh), warp tile m16 x n16 ----
    {
        const int h = wid & 3, nh = wid >> 2;
        float cl4[2][4];
#pragma unroll
        for (int t = 0; t < 2; t++)
#pragma unroll
            for (int j = 0; j < 4; j++) cl4[t][j] = 0.f;

        const uint32_t qbase = sb + OF_QH + arow * 272;
#pragma unroll
        for (int ks = 0; ks < 2; ks++) {
            const int acol = (h * 32 + ks * 16 + khalf * 8) * 2;
            uint32_t ah[4], al[4];
            ldsm4(ah[0], ah[1], ah[2], ah[3], qbase + acol);
            ldsm4(al[0], al[1], al[2], al[3], qbase + (OF_QL - OF_QH) + acol);
            const uint32_t baddr = sb + OF_KH + (nh * 16 + bn_off) * 272
                                 + (h * 32 + ks * 16 + bk_half * 8) * 2;
            uint32_t bh0, bh1, bh2, bh3, bl0, bl1, bl2, bl3;
            ldsm4(bh0, bh1, bh2, bh3, baddr);
            ldsm4(bl0, bl1, bl2, bl3, baddr + (OF_KL - OF_KH));
            mma16816(cl4[0], ah, bh0, bh1);
            mma16816(cl4[1], ah, bh2, bh3);
            mma16816(cl4[0], ah, bl0, bl1);
            mma16816(cl4[1], ah, bl2, bl3);
            mma16816(cl4[0], al, bh0, bh1);
            mma16816(cl4[1], al, bh2, bh3);
        }
        const int q0 = lane >> 2;
#pragma unroll
        for (int t8 = 0; t8 < 2; t8++) {
            int kk0 = nh * 16 + t8 * 8 + 2 * (lane & 3);
            if (kk0 < 56) {
                lg[q0 * 224 + h * 56 + kk0]           = cl4[t8][0];
                lg[q0 * 224 + h * 56 + kk0 + 1]       = cl4[t8][1];
                lg[(q0 + 8) * 224 + h * 56 + kk0]     = cl4[t8][2];
                lg[(q0 + 8) * 224 + h * 56 + kk0 + 1] = cl4[t8][3];
            }
        }
    }
    __syncthreads();

    // ---- fused softmax + head-mean, register-resident (threads 0..255) ----
    if (tid < 256) {
        const int q = tid >> 4, h = (tid >> 2) & 3, sub = tid & 3;
        const float* base = lg + q * 224 + h * 56;
        float pv[13];
        float mx = -1e30f;
#pragma unroll
        for (int j = 0; j < 13; j++) {
            int kk = sub + 4 * j;
            pv[j] = (kk < 49) ? base[kk] : -1e30f;
            mx = fmaxf(mx, pv[j]);
        }
        mx = fmaxf(mx, __shfl_xor_sync(0xffffffffu, mx, 1));
        mx = fmaxf(mx, __shfl_xor_sync(0xffffffffu, mx, 2));
        float s = 0.f;
#pragma unroll
        for (int j = 0; j < 13; j++) {
            pv[j] = __expf(pv[j] - mx);
            s += pv[j];
        }
        s += __shfl_xor_sync(0xffffffffu, s, 1);
        s += __shfl_xor_sync(0xffffffffu, s, 2);
        const float inv = 0.25f / s;
#pragma unroll
        for (int j = 0; j < 13; j++) {
            float a = pv[j] * inv;
            a += __shfl_xor_sync(0xffffffffu, a, 4);
            a += __shfl_xor_sync(0xffffffffu, a, 8);
            pv[j] = a;
        }
        if (h == 0) {
#pragma unroll
            for (int j = 0; j < 13; j++) {
                int kk = sub + 4 * j;
                if (kk < 49) {
                    unsigned short hh, ll;
                    split1(pv[j], hh, ll);
                    *(unsigned short*)(sma + OF_AMH + q * 144 + kk * 2) = hh;
                    *(unsigned short*)(sma + OF_AML + q * 144 + kk * 2) = ll;
                }
            }
        } else if (h == 1) {
            for (int kk = 49 + sub; kk < 64; kk += 4) {
                *(unsigned short*)(sma + OF_AMH + q * 144 + kk * 2) = 0;
                *(unsigned short*)(sma + OF_AML + q * 144 + kk * 2) = 0;
            }
        }
    }
    __syncthreads();

    // ---- AV: 8 warps (wid<8), warp = 16 channels, K=64; B via ldmatrix.trans ----
    if (wid < 8) {
        float co[2][4];
#pragma unroll
        for (int t = 0; t < 2; t++)
#pragma unroll
            for (int j = 0; j < 4; j++) co[t][j] = 0.f;

#pragma unroll
        for (int ks = 0; ks < 4; ks++) {
            const uint32_t aaddr = sb + OF_AMH + arow * 144 + (ks * 16 + khalf * 8) * 2;
            uint32_t ah[4], al[4];
            ldsm4(ah[0], ah[1], ah[2], ah[3], aaddr);
            ldsm4(al[0], al[1], al[2], al[3], aaddr + (OF_AML - OF_AMH));
            const uint32_t baddr = sb + OF_VH + (ks * 16 + arow) * 272
                                 + (wid * 16 + khalf * 8) * 2;
            uint32_t bh0, bh1, bh2, bh3, bl0, bl1, bl2, bl3;
            ldsm4t(bh0, bh1, bh2, bh3, baddr);
            ldsm4t(bl0, bl1, bl2, bl3, baddr + (OF_VL - OF_VH));
            mma16816(co[0], ah, bh0, bh1);
            mma16816(co[1], ah, bh2, bh3);
            mma16816(co[0], ah, bl0, bl1);
            mma16816(co[1], ah, bl2, bl3);
            mma16816(co[0], al, bh0, bh1);
            mma16816(co[1], al, bh2, bh3);
        }

        const int q0 = lane >> 2;
        const int pix0 = (by * 4 + (q0 >> 2)) * 128 + bx * 4 + (q0 & 3);
        const int q1 = q0 + 8;
        const int pix1 = (by * 4 + (q1 >> 2)) * 128 + bx * 4 + (q1 & 3);
#pragma unroll
        for (int t8 = 0; t8 < 2; t8++) {
            int cch = wid * 16 + t8 * 8 + 2 * (lane & 3);
            out[cch * 16384 + pix0]       = co[t8][0];
            out[(cch + 1) * 16384 + pix0] = co[t8][1];
            out[cch * 16384 + pix1]       = co[t8][2];
            out[(cch + 1) * 16384 + pix1] = co[t8][3];
        }
    }
}

// ---------------------------------------------------------------------------
extern "C" void kernel_launch(void* const* d_in, const int* in_sizes, int n_in,
                              void* d_out, int out_size) {
    const float* q  = (const float*)d_in[0];
    const float* k  = (const float*)d_in[1];
    const float* v  = (const float*)d_in[2];
    const float* cw = (const float*)d_in[3];
    const float* nq = (const float*)d_in[4];
    const float* nk = (const float*)d_in[5];
    const float* qw = (const float*)d_in[6];
    const float* qb = (const float*)d_in[7];
    const float* kw = (const float*)d_in[8];
    const float* kb = (const float*)d_in[9];
    float* out = (float*)d_out;

    cudaFuncSetAttribute(convq_mma, cudaFuncAttributeMaxDynamicSharedMemorySize, 173696);
    cudaFuncSetAttribute(attn_kernel, cudaFuncAttributeMaxDynamicSharedMemorySize, 97280);

    prep_kernel<<<576, 256>>>(cw, nq, nk, qw, kw);
    convq_mma<<<dim3(8, 16), 256, 173696>>>(q, qb);
    kprep_kernel<<<64, 256, 41088>>>(k, v, kb);
    attn_kernel<<<dim3(32, 32), 512, 97280>>>(out);
}